// round 5
// baseline (speedup 1.0000x reference)
#include <cuda_runtime.h>
#include <cstddef>

#define N_USERS 50000
#define N_ENT   100000
#define N_TOT   150000
#define D       64
#define E_CAP   1536000

// ---------------------------------------------------------------------------
// Scratch (device globals: no allocation allowed)
// ---------------------------------------------------------------------------
__device__ __align__(256) float g_y[(size_t)N_TOT * D];   // x @ W
__device__ float g_Z;
__device__ int g_deg[N_TOT];
__device__ int g_off[N_TOT + 1];
__device__ int g_cur[N_TOT];
__device__ int g_src_sorted[E_CAP];
__device__ int g_part[1024];

static const int NB_SCAN = (N_TOT + 255) / 256;   // 586

// ---------------------------------------------------------------------------
// sort branch step 0: zero degree histogram + Z
// ---------------------------------------------------------------------------
__global__ void init_deg_kernel() {
    int i = blockIdx.x * blockDim.x + threadIdx.x;
    if (i == 0) g_Z = 0.0f;
    int4 z4 = make_int4(0, 0, 0, 0);
    for (int j = i; j < N_TOT / 4; j += gridDim.x * blockDim.x)
        ((int4*)g_deg)[j] = z4;
}

// ---------------------------------------------------------------------------
// build branch: y = x @ W. Tile = 128 rows, block = 256 threads.
// ---------------------------------------------------------------------------
__global__ void __launch_bounds__(256) build_y_kernel(
    const int* __restrict__ uidx, const int* __restrict__ iidx,
    const float* __restrict__ ut, const float* __restrict__ et,
    const float* __restrict__ W)
{
    __shared__ float Ws[64 * 64];       // 16 KB
    __shared__ float xst[64][128];      // 32 KB, transposed

    const int tid = threadIdx.x;
    for (int i = tid; i < 1024; i += 256)
        ((float4*)Ws)[i] = ((const float4*)W)[i];

    const int row0 = blockIdx.x * 128;
    {
        const int lr = tid >> 1;
        const int lj = tid & 1;
        const int r  = row0 + lr;
        if (r < N_TOT) {
            const float* xrow;
            if (r < N_USERS) xrow = ut + (size_t)__ldg(uidx + r) * D;
            else             xrow = et + (size_t)__ldg(iidx + (r - N_USERS)) * D;
            #pragma unroll
            for (int i = 0; i < 8; i++) {
                const int c4 = lj * 8 + i;
                float4 v = ((const float4*)xrow)[c4];
                xst[c4 * 4 + 0][lr] = v.x;
                xst[c4 * 4 + 1][lr] = v.y;
                xst[c4 * 4 + 2][lr] = v.z;
                xst[c4 * 4 + 3][lr] = v.w;
            }
        }
    }
    __syncthreads();

    const int j  = tid & 15;
    const int rt = tid >> 4;

    float4 acc[8];
    #pragma unroll
    for (int r = 0; r < 8; r++) acc[r] = make_float4(0.f, 0.f, 0.f, 0.f);

    #pragma unroll 4
    for (int k = 0; k < 64; k++) {
        const float4 w  = *(const float4*)&Ws[k * 64 + j * 4];
        const float4 xa = *(const float4*)&xst[k][rt * 8];
        const float4 xb = *(const float4*)&xst[k][rt * 8 + 4];
        acc[0].x += xa.x * w.x; acc[0].y += xa.x * w.y; acc[0].z += xa.x * w.z; acc[0].w += xa.x * w.w;
        acc[1].x += xa.y * w.x; acc[1].y += xa.y * w.y; acc[1].z += xa.y * w.z; acc[1].w += xa.y * w.w;
        acc[2].x += xa.z * w.x; acc[2].y += xa.z * w.y; acc[2].z += xa.z * w.z; acc[2].w += xa.z * w.w;
        acc[3].x += xa.w * w.x; acc[3].y += xa.w * w.y; acc[3].z += xa.w * w.z; acc[3].w += xa.w * w.w;
        acc[4].x += xb.x * w.x; acc[4].y += xb.x * w.y; acc[4].z += xb.x * w.z; acc[4].w += xb.x * w.w;
        acc[5].x += xb.y * w.x; acc[5].y += xb.y * w.y; acc[5].z += xb.y * w.z; acc[5].w += xb.y * w.w;
        acc[6].x += xb.z * w.x; acc[6].y += xb.z * w.y; acc[6].z += xb.z * w.z; acc[6].w += xb.z * w.w;
        acc[7].x += xb.w * w.x; acc[7].y += xb.w * w.y; acc[7].z += xb.w * w.z; acc[7].w += xb.w * w.w;
    }

    #pragma unroll
    for (int r = 0; r < 8; r++) {
        const int row = row0 + rt * 8 + r;
        if (row < N_TOT)
            ((float4*)(g_y + (size_t)row * D))[j] = acc[r];
    }
}

// ---------------------------------------------------------------------------
// Counting sort by dst: hist (int4) -> reduce -> fused scan -> scatter (int4)
// ---------------------------------------------------------------------------
__global__ void hist_kernel(const int* __restrict__ ei, int E) {
    const int n4 = E >> 2;
    const int st = gridDim.x * blockDim.x;
    const int4* d4 = (const int4*)(ei + E);
    for (int i = blockIdx.x * blockDim.x + threadIdx.x; i < n4; i += st) {
        int4 d = __ldg(d4 + i);
        atomicAdd(&g_deg[d.x], 1); atomicAdd(&g_deg[d.y], 1);
        atomicAdd(&g_deg[d.z], 1); atomicAdd(&g_deg[d.w], 1);
    }
    for (int e = (n4 << 2) + blockIdx.x * blockDim.x + threadIdx.x; e < E; e += st)
        atomicAdd(&g_deg[__ldg(ei + E + e)], 1);
}

__global__ void __launch_bounds__(256) scan_reduce_kernel() {
    const int t = threadIdx.x;
    const int idx = blockIdx.x * 256 + t;
    int v = (idx < N_TOT) ? g_deg[idx] : 0;
    #pragma unroll
    for (int o = 16; o > 0; o >>= 1) v += __shfl_xor_sync(0xffffffffu, v, o);
    __shared__ int sw[8];
    if ((t & 31) == 0) sw[t >> 5] = v;
    __syncthreads();
    if (t == 0) {
        int s = 0;
        #pragma unroll
        for (int w = 0; w < 8; w++) s += sw[w];
        g_part[blockIdx.x] = s;
    }
}

__global__ void __launch_bounds__(256) scan_final_kernel(int nb) {
    __shared__ int s[256];
    __shared__ int sbase;
    const int t = threadIdx.x;
    const int b = blockIdx.x;

    int acc = 0;
    for (int j = t; j < b; j += 256) acc += g_part[j];
    #pragma unroll
    for (int o = 16; o > 0; o >>= 1) acc += __shfl_xor_sync(0xffffffffu, acc, o);
    __shared__ int sw[8];
    if ((t & 31) == 0) sw[t >> 5] = acc;
    __syncthreads();
    if (t == 0) {
        int ss = 0;
        #pragma unroll
        for (int w = 0; w < 8; w++) ss += sw[w];
        sbase = ss;
    }

    const int idx = b * 256 + t;
    int v = (idx < N_TOT) ? g_deg[idx] : 0;
    s[t] = v; __syncthreads();
    #pragma unroll
    for (int o = 1; o < 256; o <<= 1) {
        int x = (t >= o) ? s[t - o] : 0;
        __syncthreads();
        s[t] += x;
        __syncthreads();
    }
    const int off = sbase + s[t] - v;
    if (idx < N_TOT) {
        g_off[idx] = off;
        g_cur[idx] = off;
        if (idx == N_TOT - 1) g_off[N_TOT] = off + v;
    }
}

__global__ void scatter_kernel(const int* __restrict__ ei, int E) {
    const int n4 = E >> 2;
    const int st = gridDim.x * blockDim.x;
    const int4* s4p = (const int4*)ei;
    const int4* d4p = (const int4*)(ei + E);
    for (int i = blockIdx.x * blockDim.x + threadIdx.x; i < n4; i += st) {
        int4 sv = __ldg(s4p + i);
        int4 dv = __ldg(d4p + i);
        g_src_sorted[atomicAdd(&g_cur[dv.x], 1)] = sv.x;
        g_src_sorted[atomicAdd(&g_cur[dv.y], 1)] = sv.y;
        g_src_sorted[atomicAdd(&g_cur[dv.z], 1)] = sv.z;
        g_src_sorted[atomicAdd(&g_cur[dv.w], 1)] = sv.w;
    }
    for (int e = (n4 << 2) + blockIdx.x * blockDim.x + threadIdx.x; e < E; e += st) {
        const int d = __ldg(ei + E + e);
        g_src_sorted[atomicAdd(&g_cur[d], 1)] = __ldg(ei + e);
    }
}

// ---------------------------------------------------------------------------
// Edge pass (CSR): 16-lane group per dst, 4-edge unroll with PREDICATED loads
// (no wasted transactions on remainder) -> 4 independent gather+shuffle chains.
// ---------------------------------------------------------------------------
__global__ void __launch_bounds__(256) edge_csr_kernel(float* __restrict__ out)
{
    const int lane = threadIdx.x & 31;
    const int li   = lane & 15;
    const int half = lane >> 4;
    const unsigned mask = 0xFFFFu << (half * 16);
    const int gid  = (blockIdx.x * blockDim.x + threadIdx.x) >> 4;
    const int ng   = (gridDim.x * blockDim.x) >> 4;

    float zloc = 0.0f;

    for (int d = gid; d < N_TOT; d += ng) {
        const float4 yd = *(const float4*)(g_y + (size_t)d * D + li * 4);
        const int beg = g_off[d];
        const int end = g_off[d + 1];

        float4 acc = make_float4(0.f, 0.f, 0.f, 0.f);
        for (int i = beg; i < end; i += 4) {
            const int rem = end - i;      // >= 1
            // predicated index + row loads: inactive slots issue nothing
            int s0 = __ldg(g_src_sorted + i);
            int s1 = 0, s2 = 0, s3 = 0;
            if (rem > 1) s1 = __ldg(g_src_sorted + i + 1);
            if (rem > 2) s2 = __ldg(g_src_sorted + i + 2);
            if (rem > 3) s3 = __ldg(g_src_sorted + i + 3);

            float4 a = *(const float4*)(g_y + (size_t)s0 * D + li * 4);
            float4 b = make_float4(0.f, 0.f, 0.f, 0.f);
            float4 c = make_float4(0.f, 0.f, 0.f, 0.f);
            float4 e4 = make_float4(0.f, 0.f, 0.f, 0.f);
            if (rem > 1) b  = *(const float4*)(g_y + (size_t)s1 * D + li * 4);
            if (rem > 2) c  = *(const float4*)(g_y + (size_t)s2 * D + li * 4);
            if (rem > 3) e4 = *(const float4*)(g_y + (size_t)s3 * D + li * 4);

            float t0 = a.x * yd.x + a.y * yd.y + a.z * yd.z + a.w * yd.w;
            float t1 = b.x * yd.x + b.y * yd.y + b.z * yd.z + b.w * yd.w;
            float t2 = c.x * yd.x + c.y * yd.y + c.z * yd.z + c.w * yd.w;
            float t3 = e4.x * yd.x + e4.y * yd.y + e4.z * yd.z + e4.w * yd.w;

            #pragma unroll
            for (int o = 8; o > 0; o >>= 1) {
                t0 += __shfl_xor_sync(mask, t0, o);
                t1 += __shfl_xor_sync(mask, t1, o);
                t2 += __shfl_xor_sync(mask, t2, o);
                t3 += __shfl_xor_sync(mask, t3, o);
            }

            float p0 = __expf(t0 >= 0.f ? t0 : 0.2f * t0);
            float p1 = (rem > 1) ? __expf(t1 >= 0.f ? t1 : 0.2f * t1) : 0.f;
            float p2 = (rem > 2) ? __expf(t2 >= 0.f ? t2 : 0.2f * t2) : 0.f;
            float p3 = (rem > 3) ? __expf(t3 >= 0.f ? t3 : 0.2f * t3) : 0.f;

            if (li == 0) zloc += (p0 + p1) + (p2 + p3);

            acc.x += p0 * a.x + p1 * b.x + p2 * c.x + p3 * e4.x;
            acc.y += p0 * a.y + p1 * b.y + p2 * c.y + p3 * e4.y;
            acc.z += p0 * a.z + p1 * b.z + p2 * c.z + p3 * e4.z;
            acc.w += p0 * a.w + p1 * b.w + p2 * c.w + p3 * e4.w;
        }
        *(float4*)(out + (size_t)d * D + li * 4) = acc;
    }

    float z = zloc;
    #pragma unroll
    for (int o = 16; o > 0; o >>= 1) z += __shfl_xor_sync(0xffffffffu, z, o);
    __shared__ float sz[8];
    if (lane == 0) sz[threadIdx.x >> 5] = z;
    __syncthreads();
    if (threadIdx.x == 0) {
        float s = 0.f;
        #pragma unroll
        for (int w = 0; w < 8; w++) s += sz[w];
        atomicAdd(&g_Z, s);
    }
}

// ---------------------------------------------------------------------------
// finalize: out = relu(out) / Z
// ---------------------------------------------------------------------------
__global__ void __launch_bounds__(256) finalize_kernel(float* __restrict__ out, int n)
{
    const float invZ = 1.0f / g_Z;
    const int n4 = n >> 2;
    float4* o4 = (float4*)out;
    const int st = gridDim.x * blockDim.x;
    for (int i = blockIdx.x * blockDim.x + threadIdx.x; i < n4; i += st) {
        float4 v = o4[i];
        v.x = v.x > 0.f ? v.x * invZ : 0.f;
        v.y = v.y > 0.f ? v.y * invZ : 0.f;
        v.z = v.z > 0.f ? v.z * invZ : 0.f;
        v.w = v.w > 0.f ? v.w * invZ : 0.f;
        o4[i] = v;
    }
}

// ---------------------------------------------------------------------------
// Launch: fork-join graph — sort chain (s2) overlaps build_y (stream 0).
// ---------------------------------------------------------------------------
extern "C" void kernel_launch(void* const* d_in, const int* in_sizes, int n_in,
                              void* d_out, int out_size)
{
    const int*   uidx = (const int*)d_in[0];
    const int*   iidx = (const int*)d_in[1];
    const int*   ei   = (const int*)d_in[2];
    const float* ut   = (const float*)d_in[5];
    const float* et   = (const float*)d_in[6];
    const float* W    = (const float*)d_in[7];
    float* out = (float*)d_out;
    const int E = in_sizes[2] / 2;

    static cudaStream_t s2 = nullptr;
    static cudaEvent_t ev_fork = nullptr, ev_join = nullptr;
    if (s2 == nullptr) {
        cudaStreamCreateWithFlags(&s2, cudaStreamNonBlocking);
        cudaEventCreateWithFlags(&ev_fork, cudaEventDisableTiming);
        cudaEventCreateWithFlags(&ev_join, cudaEventDisableTiming);
    }

    cudaEventRecord(ev_fork, 0);
    cudaStreamWaitEvent(s2, ev_fork, 0);
    init_deg_kernel<<<160, 256, 0, s2>>>();
    hist_kernel<<<1184, 256, 0, s2>>>(ei, E);
    scan_reduce_kernel<<<NB_SCAN, 256, 0, s2>>>();
    scan_final_kernel<<<NB_SCAN, 256, 0, s2>>>(NB_SCAN);
    scatter_kernel<<<1184, 256, 0, s2>>>(ei, E);
    cudaEventRecord(ev_join, s2);

    build_y_kernel<<<(N_TOT + 127) / 128, 256>>>(uidx, iidx, ut, et, W);

    cudaStreamWaitEvent(0, ev_join, 0);
    edge_csr_kernel<<<1184, 256>>>(out);
    finalize_kernel<<<1184, 256>>>(out, out_size);
}

// round 6
// speedup vs baseline: 1.4521x; 1.4521x over previous
#include <cuda_runtime.h>
#include <cuda_fp16.h>
#include <cstddef>

#define N_USERS 50000
#define N_ENT   100000
#define N_TOT   150000
#define D       64
#define E_CAP   1536000

// ---------------------------------------------------------------------------
// Scratch (device globals: no allocation allowed)
// g_yh: y = x @ W stored as fp16 (sole consumer is the edge pass; output stays fp32)
// ---------------------------------------------------------------------------
__device__ __align__(256) __half g_yh[(size_t)N_TOT * D];
__device__ float g_Z;
__device__ int g_deg[N_TOT];
__device__ int g_off[N_TOT + 1];
__device__ int g_cur[N_TOT];
__device__ int g_src_sorted[E_CAP];
__device__ int g_part[1024];

static const int NB_SCAN = (N_TOT + 255) / 256;   // 586

// ---------------------------------------------------------------------------
// sort branch step 0: zero degree histogram + Z
// ---------------------------------------------------------------------------
__global__ void init_deg_kernel() {
    int i = blockIdx.x * blockDim.x + threadIdx.x;
    if (i == 0) g_Z = 0.0f;
    int4 z4 = make_int4(0, 0, 0, 0);
    for (int j = i; j < N_TOT / 4; j += gridDim.x * blockDim.x)
        ((int4*)g_deg)[j] = z4;
}

// ---------------------------------------------------------------------------
// build branch: y = x @ W (fp32 math, fp16 store). Tile = 128 rows.
// ---------------------------------------------------------------------------
__global__ void __launch_bounds__(256) build_y_kernel(
    const int* __restrict__ uidx, const int* __restrict__ iidx,
    const float* __restrict__ ut, const float* __restrict__ et,
    const float* __restrict__ W)
{
    __shared__ float Ws[64 * 64];       // 16 KB
    __shared__ float xst[64][128];      // 32 KB, transposed

    const int tid = threadIdx.x;
    for (int i = tid; i < 1024; i += 256)
        ((float4*)Ws)[i] = ((const float4*)W)[i];

    const int row0 = blockIdx.x * 128;
    {
        const int lr = tid >> 1;
        const int lj = tid & 1;
        const int r  = row0 + lr;
        if (r < N_TOT) {
            const float* xrow;
            if (r < N_USERS) xrow = ut + (size_t)__ldg(uidx + r) * D;
            else             xrow = et + (size_t)__ldg(iidx + (r - N_USERS)) * D;
            #pragma unroll
            for (int i = 0; i < 8; i++) {
                const int c4 = lj * 8 + i;
                float4 v = ((const float4*)xrow)[c4];
                xst[c4 * 4 + 0][lr] = v.x;
                xst[c4 * 4 + 1][lr] = v.y;
                xst[c4 * 4 + 2][lr] = v.z;
                xst[c4 * 4 + 3][lr] = v.w;
            }
        }
    }
    __syncthreads();

    const int j  = tid & 15;
    const int rt = tid >> 4;

    float4 acc[8];
    #pragma unroll
    for (int r = 0; r < 8; r++) acc[r] = make_float4(0.f, 0.f, 0.f, 0.f);

    #pragma unroll 4
    for (int k = 0; k < 64; k++) {
        const float4 w  = *(const float4*)&Ws[k * 64 + j * 4];
        const float4 xa = *(const float4*)&xst[k][rt * 8];
        const float4 xb = *(const float4*)&xst[k][rt * 8 + 4];
        acc[0].x += xa.x * w.x; acc[0].y += xa.x * w.y; acc[0].z += xa.x * w.z; acc[0].w += xa.x * w.w;
        acc[1].x += xa.y * w.x; acc[1].y += xa.y * w.y; acc[1].z += xa.y * w.z; acc[1].w += xa.y * w.w;
        acc[2].x += xa.z * w.x; acc[2].y += xa.z * w.y; acc[2].z += xa.z * w.z; acc[2].w += xa.z * w.w;
        acc[3].x += xa.w * w.x; acc[3].y += xa.w * w.y; acc[3].z += xa.w * w.z; acc[3].w += xa.w * w.w;
        acc[4].x += xb.x * w.x; acc[4].y += xb.x * w.y; acc[4].z += xb.x * w.z; acc[4].w += xb.x * w.w;
        acc[5].x += xb.y * w.x; acc[5].y += xb.y * w.y; acc[5].z += xb.y * w.z; acc[5].w += xb.y * w.w;
        acc[6].x += xb.z * w.x; acc[6].y += xb.z * w.y; acc[6].z += xb.z * w.z; acc[6].w += xb.z * w.w;
        acc[7].x += xb.w * w.x; acc[7].y += xb.w * w.y; acc[7].z += xb.w * w.z; acc[7].w += xb.w * w.w;
    }

    #pragma unroll
    for (int r = 0; r < 8; r++) {
        const int row = row0 + rt * 8 + r;
        if (row < N_TOT) {
            __half2 h0 = __floats2half2_rn(acc[r].x, acc[r].y);
            __half2 h1 = __floats2half2_rn(acc[r].z, acc[r].w);
            uint2 u = make_uint2(*(unsigned*)&h0, *(unsigned*)&h1);
            ((uint2*)(g_yh + (size_t)row * D))[j] = u;
        }
    }
}

// ---------------------------------------------------------------------------
// Counting sort by dst: hist (int4) -> reduce -> fused scan -> scatter (int4)
// ---------------------------------------------------------------------------
__global__ void hist_kernel(const int* __restrict__ ei, int E) {
    const int n4 = E >> 2;
    const int st = gridDim.x * blockDim.x;
    const int4* d4 = (const int4*)(ei + E);
    for (int i = blockIdx.x * blockDim.x + threadIdx.x; i < n4; i += st) {
        int4 d = __ldg(d4 + i);
        atomicAdd(&g_deg[d.x], 1); atomicAdd(&g_deg[d.y], 1);
        atomicAdd(&g_deg[d.z], 1); atomicAdd(&g_deg[d.w], 1);
    }
    for (int e = (n4 << 2) + blockIdx.x * blockDim.x + threadIdx.x; e < E; e += st)
        atomicAdd(&g_deg[__ldg(ei + E + e)], 1);
}

__global__ void __launch_bounds__(256) scan_reduce_kernel() {
    const int t = threadIdx.x;
    const int idx = blockIdx.x * 256 + t;
    int v = (idx < N_TOT) ? g_deg[idx] : 0;
    #pragma unroll
    for (int o = 16; o > 0; o >>= 1) v += __shfl_xor_sync(0xffffffffu, v, o);
    __shared__ int sw[8];
    if ((t & 31) == 0) sw[t >> 5] = v;
    __syncthreads();
    if (t == 0) {
        int s = 0;
        #pragma unroll
        for (int w = 0; w < 8; w++) s += sw[w];
        g_part[blockIdx.x] = s;
    }
}

__global__ void __launch_bounds__(256) scan_final_kernel(int nb) {
    __shared__ int s[256];
    __shared__ int sbase;
    const int t = threadIdx.x;
    const int b = blockIdx.x;

    int acc = 0;
    for (int j = t; j < b; j += 256) acc += g_part[j];
    #pragma unroll
    for (int o = 16; o > 0; o >>= 1) acc += __shfl_xor_sync(0xffffffffu, acc, o);
    __shared__ int sw[8];
    if ((t & 31) == 0) sw[t >> 5] = acc;
    __syncthreads();
    if (t == 0) {
        int ss = 0;
        #pragma unroll
        for (int w = 0; w < 8; w++) ss += sw[w];
        sbase = ss;
    }

    const int idx = b * 256 + t;
    int v = (idx < N_TOT) ? g_deg[idx] : 0;
    s[t] = v; __syncthreads();
    #pragma unroll
    for (int o = 1; o < 256; o <<= 1) {
        int x = (t >= o) ? s[t - o] : 0;
        __syncthreads();
        s[t] += x;
        __syncthreads();
    }
    const int off = sbase + s[t] - v;
    if (idx < N_TOT) {
        g_off[idx] = off;
        g_cur[idx] = off;
        if (idx == N_TOT - 1) g_off[N_TOT] = off + v;
    }
}

__global__ void scatter_kernel(const int* __restrict__ ei, int E) {
    const int n4 = E >> 2;
    const int st = gridDim.x * blockDim.x;
    const int4* s4p = (const int4*)ei;
    const int4* d4p = (const int4*)(ei + E);
    for (int i = blockIdx.x * blockDim.x + threadIdx.x; i < n4; i += st) {
        int4 sv = __ldg(s4p + i);
        int4 dv = __ldg(d4p + i);
        g_src_sorted[atomicAdd(&g_cur[dv.x], 1)] = sv.x;
        g_src_sorted[atomicAdd(&g_cur[dv.y], 1)] = sv.y;
        g_src_sorted[atomicAdd(&g_cur[dv.z], 1)] = sv.z;
        g_src_sorted[atomicAdd(&g_cur[dv.w], 1)] = sv.w;
    }
    for (int e = (n4 << 2) + blockIdx.x * blockDim.x + threadIdx.x; e < E; e += st) {
        const int d = __ldg(ei + E + e);
        g_src_sorted[atomicAdd(&g_cur[d], 1)] = __ldg(ei + e);
    }
}

// ---------------------------------------------------------------------------
// Edge pass (CSR): 16-lane group per dst, fp16 gathers (8B/lane), 2-edge
// unroll (R4 structure — the 4-unroll regressed in R5).
// ---------------------------------------------------------------------------
__global__ void __launch_bounds__(256) edge_csr_kernel(float* __restrict__ out)
{
    const int lane = threadIdx.x & 31;
    const int li   = lane & 15;
    const int half = lane >> 4;
    const unsigned mask = 0xFFFFu << (half * 16);
    const int gid  = (blockIdx.x * blockDim.x + threadIdx.x) >> 4;
    const int ng   = (gridDim.x * blockDim.x) >> 4;

    float zloc = 0.0f;

    for (int d = gid; d < N_TOT; d += ng) {
        // own dst slice: 4 halves -> 4 floats
        float2 yd0, yd1;
        {
            uint2 u = __ldg((const uint2*)(g_yh + (size_t)d * D) + li);
            yd0 = __half22float2(*(__half2*)&u.x);
            yd1 = __half22float2(*(__half2*)&u.y);
        }
        const int beg = g_off[d];
        const int end = g_off[d + 1];

        float4 acc = make_float4(0.f, 0.f, 0.f, 0.f);
        int i = beg;
        for (; i + 2 <= end; i += 2) {
            const int s0 = __ldg(g_src_sorted + i);
            const int s1 = __ldg(g_src_sorted + i + 1);
            uint2 ua = __ldg((const uint2*)(g_yh + (size_t)s0 * D) + li);
            uint2 ub = __ldg((const uint2*)(g_yh + (size_t)s1 * D) + li);
            float2 a0 = __half22float2(*(__half2*)&ua.x);
            float2 a1 = __half22float2(*(__half2*)&ua.y);
            float2 b0 = __half22float2(*(__half2*)&ub.x);
            float2 b1 = __half22float2(*(__half2*)&ub.y);

            float t0 = a0.x * yd0.x + a0.y * yd0.y + a1.x * yd1.x + a1.y * yd1.y;
            float t1 = b0.x * yd0.x + b0.y * yd0.y + b1.x * yd1.x + b1.y * yd1.y;
            t0 += __shfl_xor_sync(mask, t0, 8);  t1 += __shfl_xor_sync(mask, t1, 8);
            t0 += __shfl_xor_sync(mask, t0, 4);  t1 += __shfl_xor_sync(mask, t1, 4);
            t0 += __shfl_xor_sync(mask, t0, 2);  t1 += __shfl_xor_sync(mask, t1, 2);
            t0 += __shfl_xor_sync(mask, t0, 1);  t1 += __shfl_xor_sync(mask, t1, 1);
            const float p0 = __expf(t0 >= 0.f ? t0 : 0.2f * t0);
            const float p1 = __expf(t1 >= 0.f ? t1 : 0.2f * t1);
            if (li == 0) zloc += p0 + p1;
            acc.x += p0 * a0.x + p1 * b0.x;
            acc.y += p0 * a0.y + p1 * b0.y;
            acc.z += p0 * a1.x + p1 * b1.x;
            acc.w += p0 * a1.y + p1 * b1.y;
        }
        if (i < end) {
            const int s0 = __ldg(g_src_sorted + i);
            uint2 ua = __ldg((const uint2*)(g_yh + (size_t)s0 * D) + li);
            float2 a0 = __half22float2(*(__half2*)&ua.x);
            float2 a1 = __half22float2(*(__half2*)&ua.y);
            float t0 = a0.x * yd0.x + a0.y * yd0.y + a1.x * yd1.x + a1.y * yd1.y;
            t0 += __shfl_xor_sync(mask, t0, 8);
            t0 += __shfl_xor_sync(mask, t0, 4);
            t0 += __shfl_xor_sync(mask, t0, 2);
            t0 += __shfl_xor_sync(mask, t0, 1);
            const float p0 = __expf(t0 >= 0.f ? t0 : 0.2f * t0);
            if (li == 0) zloc += p0;
            acc.x += p0 * a0.x; acc.y += p0 * a0.y;
            acc.z += p0 * a1.x; acc.w += p0 * a1.y;
        }
        *(float4*)(out + (size_t)d * D + li * 4) = acc;
    }

    float z = zloc;
    #pragma unroll
    for (int o = 16; o > 0; o >>= 1) z += __shfl_xor_sync(0xffffffffu, z, o);
    __shared__ float sz[8];
    if (lane == 0) sz[threadIdx.x >> 5] = z;
    __syncthreads();
    if (threadIdx.x == 0) {
        float s = 0.f;
        #pragma unroll
        for (int w = 0; w < 8; w++) s += sz[w];
        atomicAdd(&g_Z, s);
    }
}

// ---------------------------------------------------------------------------
// finalize: out = relu(out) / Z
// ---------------------------------------------------------------------------
__global__ void __launch_bounds__(256) finalize_kernel(float* __restrict__ out, int n)
{
    const float invZ = 1.0f / g_Z;
    const int n4 = n >> 2;
    float4* o4 = (float4*)out;
    const int st = gridDim.x * blockDim.x;
    for (int i = blockIdx.x * blockDim.x + threadIdx.x; i < n4; i += st) {
        float4 v = o4[i];
        v.x = v.x > 0.f ? v.x * invZ : 0.f;
        v.y = v.y > 0.f ? v.y * invZ : 0.f;
        v.z = v.z > 0.f ? v.z * invZ : 0.f;
        v.w = v.w > 0.f ? v.w * invZ : 0.f;
        o4[i] = v;
    }
}

// ---------------------------------------------------------------------------
// Launch: fork-join — sort chain (s2) overlaps build_y (stream 0).
// ---------------------------------------------------------------------------
extern "C" void kernel_launch(void* const* d_in, const int* in_sizes, int n_in,
                              void* d_out, int out_size)
{
    const int*   uidx = (const int*)d_in[0];
    const int*   iidx = (const int*)d_in[1];
    const int*   ei   = (const int*)d_in[2];
    const float* ut   = (const float*)d_in[5];
    const float* et   = (const float*)d_in[6];
    const float* W    = (const float*)d_in[7];
    float* out = (float*)d_out;
    const int E = in_sizes[2] / 2;

    static cudaStream_t s2 = nullptr;
    static cudaEvent_t ev_fork = nullptr, ev_join = nullptr;
    if (s2 == nullptr) {
        cudaStreamCreateWithFlags(&s2, cudaStreamNonBlocking);
        cudaEventCreateWithFlags(&ev_fork, cudaEventDisableTiming);
        cudaEventCreateWithFlags(&ev_join, cudaEventDisableTiming);
    }

    cudaEventRecord(ev_fork, 0);
    cudaStreamWaitEvent(s2, ev_fork, 0);
    init_deg_kernel<<<160, 256, 0, s2>>>();
    hist_kernel<<<592, 256, 0, s2>>>(ei, E);
    scan_reduce_kernel<<<NB_SCAN, 256, 0, s2>>>();
    scan_final_kernel<<<NB_SCAN, 256, 0, s2>>>(NB_SCAN);
    scatter_kernel<<<592, 256, 0, s2>>>(ei, E);
    cudaEventRecord(ev_join, s2);

    build_y_kernel<<<(N_TOT + 127) / 128, 256>>>(uidx, iidx, ut, et, W);

    cudaStreamWaitEvent(0, ev_join, 0);
    edge_csr_kernel<<<1184, 256>>>(out);
    finalize_kernel<<<1184, 256>>>(out, out_size);
}

// round 7
// speedup vs baseline: 1.4768x; 1.0170x over previous
#include <cuda_runtime.h>
#include <cuda_fp16.h>
#include <cstddef>

#define N_USERS 50000
#define N_ENT   100000
#define N_TOT   150000
#define D       64
#define E_CAP   1536000

// ---------------------------------------------------------------------------
// Scratch (device globals: no allocation allowed)
// ---------------------------------------------------------------------------
__device__ __align__(256) __half g_yh[(size_t)N_TOT * D];
__device__ float g_Z;
__device__ int g_deg[N_TOT];
__device__ int g_off[N_TOT + 1];
__device__ int g_cur[N_TOT];
__device__ int g_src_sorted[E_CAP];
__device__ int g_part[1024];

static const int NB_SCAN = (N_TOT + 255) / 256;   // 586

// ---------------------------------------------------------------------------
// sort branch step 0: zero degree histogram + Z
// ---------------------------------------------------------------------------
__global__ void init_deg_kernel() {
    int i = blockIdx.x * blockDim.x + threadIdx.x;
    if (i == 0) g_Z = 0.0f;
    int4 z4 = make_int4(0, 0, 0, 0);
    for (int j = i; j < N_TOT / 4; j += gridDim.x * blockDim.x)
        ((int4*)g_deg)[j] = z4;
}

// ---------------------------------------------------------------------------
// build branch: y = x @ W (fp32 math, fp16 store). Tile = 128 rows.
// ---------------------------------------------------------------------------
__global__ void __launch_bounds__(256) build_y_kernel(
    const int* __restrict__ uidx, const int* __restrict__ iidx,
    const float* __restrict__ ut, const float* __restrict__ et,
    const float* __restrict__ W)
{
    __shared__ float Ws[64 * 64];
    __shared__ float xst[64][128];

    const int tid = threadIdx.x;
    for (int i = tid; i < 1024; i += 256)
        ((float4*)Ws)[i] = ((const float4*)W)[i];

    const int row0 = blockIdx.x * 128;
    {
        const int lr = tid >> 1;
        const int lj = tid & 1;
        const int r  = row0 + lr;
        if (r < N_TOT) {
            const float* xrow;
            if (r < N_USERS) xrow = ut + (size_t)__ldg(uidx + r) * D;
            else             xrow = et + (size_t)__ldg(iidx + (r - N_USERS)) * D;
            #pragma unroll
            for (int i = 0; i < 8; i++) {
                const int c4 = lj * 8 + i;
                float4 v = ((const float4*)xrow)[c4];
                xst[c4 * 4 + 0][lr] = v.x;
                xst[c4 * 4 + 1][lr] = v.y;
                xst[c4 * 4 + 2][lr] = v.z;
                xst[c4 * 4 + 3][lr] = v.w;
            }
        }
    }
    __syncthreads();

    const int j  = tid & 15;
    const int rt = tid >> 4;

    float4 acc[8];
    #pragma unroll
    for (int r = 0; r < 8; r++) acc[r] = make_float4(0.f, 0.f, 0.f, 0.f);

    #pragma unroll 4
    for (int k = 0; k < 64; k++) {
        const float4 w  = *(const float4*)&Ws[k * 64 + j * 4];
        const float4 xa = *(const float4*)&xst[k][rt * 8];
        const float4 xb = *(const float4*)&xst[k][rt * 8 + 4];
        acc[0].x += xa.x * w.x; acc[0].y += xa.x * w.y; acc[0].z += xa.x * w.z; acc[0].w += xa.x * w.w;
        acc[1].x += xa.y * w.x; acc[1].y += xa.y * w.y; acc[1].z += xa.y * w.z; acc[1].w += xa.y * w.w;
        acc[2].x += xa.z * w.x; acc[2].y += xa.z * w.y; acc[2].z += xa.z * w.z; acc[2].w += xa.z * w.w;
        acc[3].x += xa.w * w.x; acc[3].y += xa.w * w.y; acc[3].z += xa.w * w.z; acc[3].w += xa.w * w.w;
        acc[4].x += xb.x * w.x; acc[4].y += xb.x * w.y; acc[4].z += xb.x * w.z; acc[4].w += xb.x * w.w;
        acc[5].x += xb.y * w.x; acc[5].y += xb.y * w.y; acc[5].z += xb.y * w.z; acc[5].w += xb.y * w.w;
        acc[6].x += xb.z * w.x; acc[6].y += xb.z * w.y; acc[6].z += xb.z * w.z; acc[6].w += xb.z * w.w;
        acc[7].x += xb.w * w.x; acc[7].y += xb.w * w.y; acc[7].z += xb.w * w.z; acc[7].w += xb.w * w.w;
    }

    #pragma unroll
    for (int r = 0; r < 8; r++) {
        const int row = row0 + rt * 8 + r;
        if (row < N_TOT) {
            __half2 h0 = __floats2half2_rn(acc[r].x, acc[r].y);
            __half2 h1 = __floats2half2_rn(acc[r].z, acc[r].w);
            uint2 u = make_uint2(*(unsigned*)&h0, *(unsigned*)&h1);
            ((uint2*)(g_yh + (size_t)row * D))[j] = u;
        }
    }
}

// ---------------------------------------------------------------------------
// Counting sort by dst: hist (int4) -> reduce -> fused scan -> scatter (int4)
// ---------------------------------------------------------------------------
__global__ void hist_kernel(const int* __restrict__ ei, int E) {
    const int n4 = E >> 2;
    const int st = gridDim.x * blockDim.x;
    const int4* d4 = (const int4*)(ei + E);
    for (int i = blockIdx.x * blockDim.x + threadIdx.x; i < n4; i += st) {
        int4 d = __ldg(d4 + i);
        atomicAdd(&g_deg[d.x], 1); atomicAdd(&g_deg[d.y], 1);
        atomicAdd(&g_deg[d.z], 1); atomicAdd(&g_deg[d.w], 1);
    }
    for (int e = (n4 << 2) + blockIdx.x * blockDim.x + threadIdx.x; e < E; e += st)
        atomicAdd(&g_deg[__ldg(ei + E + e)], 1);
}

__global__ void __launch_bounds__(256) scan_reduce_kernel() {
    const int t = threadIdx.x;
    const int idx = blockIdx.x * 256 + t;
    int v = (idx < N_TOT) ? g_deg[idx] : 0;
    #pragma unroll
    for (int o = 16; o > 0; o >>= 1) v += __shfl_xor_sync(0xffffffffu, v, o);
    __shared__ int sw[8];
    if ((t & 31) == 0) sw[t >> 5] = v;
    __syncthreads();
    if (t == 0) {
        int s = 0;
        #pragma unroll
        for (int w = 0; w < 8; w++) s += sw[w];
        g_part[blockIdx.x] = s;
    }
}

__global__ void __launch_bounds__(256) scan_final_kernel(int nb) {
    __shared__ int s[256];
    __shared__ int sbase;
    const int t = threadIdx.x;
    const int b = blockIdx.x;

    int acc = 0;
    for (int j = t; j < b; j += 256) acc += g_part[j];
    #pragma unroll
    for (int o = 16; o > 0; o >>= 1) acc += __shfl_xor_sync(0xffffffffu, acc, o);
    __shared__ int sw[8];
    if ((t & 31) == 0) sw[t >> 5] = acc;
    __syncthreads();
    if (t == 0) {
        int ss = 0;
        #pragma unroll
        for (int w = 0; w < 8; w++) ss += sw[w];
        sbase = ss;
    }

    const int idx = b * 256 + t;
    int v = (idx < N_TOT) ? g_deg[idx] : 0;
    s[t] = v; __syncthreads();
    #pragma unroll
    for (int o = 1; o < 256; o <<= 1) {
        int x = (t >= o) ? s[t - o] : 0;
        __syncthreads();
        s[t] += x;
        __syncthreads();
    }
    const int off = sbase + s[t] - v;
    if (idx < N_TOT) {
        g_off[idx] = off;
        g_cur[idx] = off;
        if (idx == N_TOT - 1) g_off[N_TOT] = off + v;
    }
}

__global__ void scatter_kernel(const int* __restrict__ ei, int E) {
    const int n4 = E >> 2;
    const int st = gridDim.x * blockDim.x;
    const int4* s4p = (const int4*)ei;
    const int4* d4p = (const int4*)(ei + E);
    for (int i = blockIdx.x * blockDim.x + threadIdx.x; i < n4; i += st) {
        int4 sv = __ldg(s4p + i);
        int4 dv = __ldg(d4p + i);
        g_src_sorted[atomicAdd(&g_cur[dv.x], 1)] = sv.x;
        g_src_sorted[atomicAdd(&g_cur[dv.y], 1)] = sv.y;
        g_src_sorted[atomicAdd(&g_cur[dv.z], 1)] = sv.z;
        g_src_sorted[atomicAdd(&g_cur[dv.w], 1)] = sv.w;
    }
    for (int e = (n4 << 2) + blockIdx.x * blockDim.x + threadIdx.x; e < E; e += st) {
        const int d = __ldg(ei + E + e);
        g_src_sorted[atomicAdd(&g_cur[d], 1)] = __ldg(ei + e);
    }
}

// ---------------------------------------------------------------------------
// Edge pass (CSR): ONE WARP per dst. Halves process edge pairs (i, i+1) of the
// SAME node -> uniform trip count (no divergence), and each SHFL covers both
// halves (2 SHFL/edge). Branchless odd-degree tail via min-clamp + p=0 mask.
// ---------------------------------------------------------------------------
__global__ void __launch_bounds__(256) edge_csr_kernel(float* __restrict__ out)
{
    const int lane = threadIdx.x & 31;
    const int li   = lane & 15;          // lane within half
    const int half = lane >> 4;          // 0 or 1
    const int wid  = (blockIdx.x * blockDim.x + threadIdx.x) >> 5;
    const int nw   = (gridDim.x * blockDim.x) >> 5;

    float zloc = 0.0f;

    for (int d = wid; d < N_TOT; d += nw) {
        // both halves load the node's own row (broadcast within half)
        float2 yd0, yd1;
        {
            uint2 u = __ldg((const uint2*)(g_yh + (size_t)d * D) + li);
            yd0 = __half22float2(*(__half2*)&u.x);
            yd1 = __half22float2(*(__half2*)&u.y);
        }
        const int beg = g_off[d];
        const int end = g_off[d + 1];
        const int npairs = (end - beg + 1) >> 1;

        float4 acc = make_float4(0.f, 0.f, 0.f, 0.f);
        for (int it = 0; it < npairs; it++) {
            const int i  = beg + it * 2 + half;
            const bool valid = (i < end);
            const int i2 = valid ? i : (end - 1);     // safe: npairs>=1 => end>beg
            const int s  = __ldg(g_src_sorted + i2);

            uint2 u = __ldg((const uint2*)(g_yh + (size_t)s * D) + li);
            float2 a0 = __half22float2(*(__half2*)&u.x);
            float2 a1 = __half22float2(*(__half2*)&u.y);

            float t = a0.x * yd0.x + a0.y * yd0.y + a1.x * yd1.x + a1.y * yd1.y;
            // xor offsets 8,4,2,1 stay within each 16-lane half
            t += __shfl_xor_sync(0xffffffffu, t, 8);
            t += __shfl_xor_sync(0xffffffffu, t, 4);
            t += __shfl_xor_sync(0xffffffffu, t, 2);
            t += __shfl_xor_sync(0xffffffffu, t, 1);

            float p = __expf(t >= 0.f ? t : 0.2f * t);
            p = valid ? p : 0.f;

            if (li == 0) zloc += p;
            acc.x += p * a0.x; acc.y += p * a0.y;
            acc.z += p * a1.x; acc.w += p * a1.y;
        }

        // merge the two halves (lane li of half0 += lane li of half1)
        acc.x += __shfl_xor_sync(0xffffffffu, acc.x, 16);
        acc.y += __shfl_xor_sync(0xffffffffu, acc.y, 16);
        acc.z += __shfl_xor_sync(0xffffffffu, acc.z, 16);
        acc.w += __shfl_xor_sync(0xffffffffu, acc.w, 16);
        if (half == 0)
            *(float4*)(out + (size_t)d * D + li * 4) = acc;
    }

    float z = zloc;
    #pragma unroll
    for (int o = 16; o > 0; o >>= 1) z += __shfl_xor_sync(0xffffffffu, z, o);
    __shared__ float sz[8];
    if (lane == 0) sz[threadIdx.x >> 5] = z;
    __syncthreads();
    if (threadIdx.x == 0) {
        float s = 0.f;
        #pragma unroll
        for (int w = 0; w < 8; w++) s += sz[w];
        atomicAdd(&g_Z, s);
    }
}

// ---------------------------------------------------------------------------
// finalize: out = relu(out) / Z
// ---------------------------------------------------------------------------
__global__ void __launch_bounds__(256) finalize_kernel(float* __restrict__ out, int n)
{
    const float invZ = 1.0f / g_Z;
    const int n4 = n >> 2;
    float4* o4 = (float4*)out;
    const int st = gridDim.x * blockDim.x;
    for (int i = blockIdx.x * blockDim.x + threadIdx.x; i < n4; i += st) {
        float4 v = o4[i];
        v.x = v.x > 0.f ? v.x * invZ : 0.f;
        v.y = v.y > 0.f ? v.y * invZ : 0.f;
        v.z = v.z > 0.f ? v.z * invZ : 0.f;
        v.w = v.w > 0.f ? v.w * invZ : 0.f;
        o4[i] = v;
    }
}

// ---------------------------------------------------------------------------
// Launch: fork-join — sort chain (s2) overlaps build_y (stream 0).
// ---------------------------------------------------------------------------
extern "C" void kernel_launch(void* const* d_in, const int* in_sizes, int n_in,
                              void* d_out, int out_size)
{
    const int*   uidx = (const int*)d_in[0];
    const int*   iidx = (const int*)d_in[1];
    const int*   ei   = (const int*)d_in[2];
    const float* ut   = (const float*)d_in[5];
    const float* et   = (const float*)d_in[6];
    const float* W    = (const float*)d_in[7];
    float* out = (float*)d_out;
    const int E = in_sizes[2] / 2;

    static cudaStream_t s2 = nullptr;
    static cudaEvent_t ev_fork = nullptr, ev_join = nullptr;
    if (s2 == nullptr) {
        cudaStreamCreateWithFlags(&s2, cudaStreamNonBlocking);
        cudaEventCreateWithFlags(&ev_fork, cudaEventDisableTiming);
        cudaEventCreateWithFlags(&ev_join, cudaEventDisableTiming);
    }

    cudaEventRecord(ev_fork, 0);
    cudaStreamWaitEvent(s2, ev_fork, 0);
    init_deg_kernel<<<160, 256, 0, s2>>>();
    hist_kernel<<<592, 256, 0, s2>>>(ei, E);
    scan_reduce_kernel<<<NB_SCAN, 256, 0, s2>>>();
    scan_final_kernel<<<NB_SCAN, 256, 0, s2>>>(NB_SCAN);
    scatter_kernel<<<592, 256, 0, s2>>>(ei, E);
    cudaEventRecord(ev_join, s2);

    build_y_kernel<<<(N_TOT + 127) / 128, 256>>>(uidx, iidx, ut, et, W);

    cudaStreamWaitEvent(0, ev_join, 0);
    edge_csr_kernel<<<1184, 256>>>(out);
    finalize_kernel<<<1184, 256>>>(out, out_size);
}